// round 11
// baseline (speedup 1.0000x reference)
#include <cuda_runtime.h>
#include <stdint.h>

#define N_NODES 50000
#define N_PAD   50048   // multiple of 128 for k_h2 tiling
#define N_EDGES 800000
#define HID     128
#define OUTC    64

// ---- scratch (device globals, zero-initialized at module load; k_gather2
//      re-zeroes g_deg/g_total each call so every replay starts clean).
//      All node arrays padded to N_PAD; pad entries stay 0 (deg=0, dinv=0,
//      xw=0) so the fused h2 prologue needs no bounds checks. ----
__device__ int   g_deg[N_PAD];
__device__ int   g_rowstart[N_PAD];
__device__ int   g_wpos[N_PAD];
__device__ int   g_csrc[N_EDGES];
__device__ int   g_total;
__device__ float g_dinv[N_PAD];
__device__ __align__(16) float g_xw[N_PAD * 4];      // x * dinv, packed float4
__device__ __align__(16) float g_h2w[N_PAD * OUTC];  // h2 * dinv

#define PACK2(d, lo, hi) asm("mov.b64 %0, {%1, %2};" : "=l"(d) : "f"(lo), "f"(hi))
#define UNPACK2(lo, hi, s) asm("mov.b64 {%0, %1}, %2;" : "=f"(lo), "=f"(hi) : "l"(s))
#define FMA2(d, a, b, c) asm("fma.rn.f32x2 %0, %1, %2, %3;" : "=l"(d) : "l"(a), "l"(b), "l"(c))

// 1) degree histogram on dst (REDG, no return); 2 edges/thread (best measured)
__global__ void k_deg(const int* __restrict__ ei) {
    int t = blockIdx.x * blockDim.x + threadIdx.x;
    if (t >= N_EDGES / 2) return;
    int2 d = ((const int2*)(ei + N_EDGES))[t];
    atomicAdd(&g_deg[d.x], 1);
    atomicAdd(&g_deg[d.y], 1);
}

// 2) row allocation (warp scan + 1 atomic/warp) + dinv + premultiplied xw
__global__ void k_assign(const float* __restrict__ x) {
    int i = blockIdx.x * blockDim.x + threadIdx.x;
    int lane = threadIdx.x & 31;
    int deg = (i < N_NODES) ? g_deg[i] : 0;
    int incl = deg;
    #pragma unroll
    for (int o = 1; o < 32; o <<= 1) {
        int v = __shfl_up_sync(0xffffffff, incl, o);
        if (lane >= o) incl += v;
    }
    int base = 0;
    if (lane == 31) base = atomicAdd(&g_total, incl);   // incl@31 = warp total
    base = __shfl_sync(0xffffffff, base, 31);
    if (i < N_NODES) {
        int rs = base + incl - deg;
        g_rowstart[i] = rs;
        g_wpos[i] = rs;
        float dd = rsqrtf((float)(deg + 1));
        g_dinv[i] = dd;
        float4 xw;
        xw.x = __ldg(&x[i * 3 + 0]) * dd;
        xw.y = __ldg(&x[i * 3 + 1]) * dd;
        xw.z = __ldg(&x[i * 3 + 2]) * dd;
        xw.w = 0.f;
        ((float4*)g_xw)[i] = xw;
    }
}

// 3) CSR scatter: src indices grouped by dst; 2 edges/thread (best measured)
__global__ void k_csr(const int* __restrict__ ei) {
    int t = blockIdx.x * blockDim.x + threadIdx.x;
    if (t >= N_EDGES / 2) return;
    int2 s = ((const int2*)ei)[t];
    int2 d = ((const int2*)(ei + N_EDGES))[t];
    int p0 = atomicAdd(&g_wpos[d.x], 1);
    g_csrc[p0] = s.x;
    int p1 = atomicAdd(&g_wpos[d.y], 1);
    g_csrc[p1] = s.y;
}

// 4) FUSED: layer-1 gather (2 threads/node into smem) + h1 = relu(v@W1+b1)
//    (smem k-major) + h2 = h1 @ W2 via fma.rn.f32x2; epilogue stores
//    h2w = h2 * dinv. Gather phase of one resident block overlaps the FMA
//    phase of its SM co-resident block.
__global__ void __launch_bounds__(256) k_h2(const float* __restrict__ W1,
                                            const float* __restrict__ b1,
                                            const float* __restrict__ W2) {
    __shared__ float4 sW2[HID * 16];    // 32 KB
    __shared__ float  sh1T[HID * 128];  // 64 KB, [k][node]
    __shared__ float4 sv[128];          // 2 KB, gathered layer-1 vectors
    int tid = threadIdx.x;
    int nodeBase = blockIdx.x * 128;

    // --- phase A: W2 -> smem ---
    #pragma unroll 4
    for (int i = tid; i < HID * 16; i += 256) sW2[i] = ((const float4*)W2)[i];

    // --- phase B: gather layer-1 sums; 2 threads per node, stride-2 edges ---
    {
        int node = tid >> 1;            // 0..127
        int half = tid & 1;
        int gnode = nodeBase + node;    // pad nodes: deg=0, rowstart=0 -> empty
        int row = g_rowstart[gnode];
        int end = row + g_deg[gnode];
        float a0 = 0.f, a1 = 0.f, a2 = 0.f;
        int e = row + half;
        for (; e + 6 < end; e += 8) {   // 4 independent loads in flight
            float4 v0 = ((const float4*)g_xw)[g_csrc[e]];
            float4 v1 = ((const float4*)g_xw)[g_csrc[e + 2]];
            float4 v2 = ((const float4*)g_xw)[g_csrc[e + 4]];
            float4 v3 = ((const float4*)g_xw)[g_csrc[e + 6]];
            a0 += (v0.x + v1.x) + (v2.x + v3.x);
            a1 += (v0.y + v1.y) + (v2.y + v3.y);
            a2 += (v0.z + v1.z) + (v2.z + v3.z);
        }
        for (; e < end; e += 2) {
            float4 v = ((const float4*)g_xw)[g_csrc[e]];
            a0 += v.x;
            a1 += v.y;
            a2 += v.z;
        }
        a0 += __shfl_xor_sync(0xffffffff, a0, 1);
        a1 += __shfl_xor_sync(0xffffffff, a1, 1);
        a2 += __shfl_xor_sync(0xffffffff, a2, 1);
        if (half == 0) {
            float4 self = ((const float4*)g_xw)[gnode];
            float dd = g_dinv[gnode];
            sv[node] = make_float4((a0 + self.x) * dd,
                                   (a1 + self.y) * dd,
                                   (a2 + self.z) * dd, 0.f);
        }
    }
    __syncthreads();

    // --- phase C: h1 = relu(v@W1 + b1) into smem, k-major ---
    #pragma unroll 4
    for (int i = tid; i < 128 * 32; i += 256) {
        int node = i & 127;
        int q    = i >> 7;
        float4 v  = sv[node];
        float4 w0 = __ldg(&((const float4*)W1)[0 * 32 + q]);
        float4 w1 = __ldg(&((const float4*)W1)[1 * 32 + q]);
        float4 w2 = __ldg(&((const float4*)W1)[2 * 32 + q]);
        float4 bq = __ldg(&((const float4*)b1)[q]);
        sh1T[(4 * q + 0) * 128 + node] = fmaxf(fmaf(v.x, w0.x, fmaf(v.y, w1.x, fmaf(v.z, w2.x, bq.x))), 0.f);
        sh1T[(4 * q + 1) * 128 + node] = fmaxf(fmaf(v.x, w0.y, fmaf(v.y, w1.y, fmaf(v.z, w2.y, bq.y))), 0.f);
        sh1T[(4 * q + 2) * 128 + node] = fmaxf(fmaf(v.x, w0.z, fmaf(v.y, w1.z, fmaf(v.z, w2.z, bq.z))), 0.f);
        sh1T[(4 * q + 3) * 128 + node] = fmaxf(fmaf(v.x, w0.w, fmaf(v.y, w1.w, fmaf(v.z, w2.w, bq.w))), 0.f);
    }
    __syncthreads();

    // --- phase D: h2 = h1 @ W2 (packed f32x2 over node pairs) ---
    int c  = tid & 15;        // cols 4c..4c+3
    int m0 = (tid >> 4) * 8;  // nodes m0..m0+7 (4 packed pairs)

    unsigned long long acc[4][4];
    #pragma unroll
    for (int p = 0; p < 4; p++)
        #pragma unroll
        for (int cc = 0; cc < 4; cc++) acc[p][cc] = 0ull;

    #pragma unroll 2
    for (int kb = 0; kb < HID; kb += 4) {
        #pragma unroll
        for (int kk = 0; kk < 4; kk++) {
            int k = kb + kk;
            float4 w = sW2[k * 16 + c];
            unsigned long long wp[4];
            PACK2(wp[0], w.x, w.x);
            PACK2(wp[1], w.y, w.y);
            PACK2(wp[2], w.z, w.z);
            PACK2(wp[3], w.w, w.w);
            float4 ha = *(const float4*)&sh1T[k * 128 + m0];
            float4 hb = *(const float4*)&sh1T[k * 128 + m0 + 4];
            unsigned long long hp[4];
            PACK2(hp[0], ha.x, ha.y);
            PACK2(hp[1], ha.z, ha.w);
            PACK2(hp[2], hb.x, hb.y);
            PACK2(hp[3], hb.z, hb.w);
            #pragma unroll
            for (int p = 0; p < 4; p++) {
                FMA2(acc[p][0], hp[p], wp[0], acc[p][0]);
                FMA2(acc[p][1], hp[p], wp[1], acc[p][1]);
                FMA2(acc[p][2], hp[p], wp[2], acc[p][2]);
                FMA2(acc[p][3], hp[p], wp[3], acc[p][3]);
            }
        }
    }

    #pragma unroll
    for (int p = 0; p < 4; p++) {
        int n0 = nodeBase + m0 + 2 * p;
        float d0 = g_dinv[n0];
        float d1 = g_dinv[n0 + 1];
        float4 r0, r1;
        UNPACK2(r0.x, r1.x, acc[p][0]);
        UNPACK2(r0.y, r1.y, acc[p][1]);
        UNPACK2(r0.z, r1.z, acc[p][2]);
        UNPACK2(r0.w, r1.w, acc[p][3]);
        r0.x *= d0; r0.y *= d0; r0.z *= d0; r0.w *= d0;
        r1.x *= d1; r1.y *= d1; r1.z *= d1; r1.w *= d1;
        ((float4*)g_h2w)[(size_t)n0 * 16 + c] = r0;
        ((float4*)g_h2w)[(size_t)(n0 + 1) * 16 + c] = r1;
    }
}

// 5) layer-2 gather, 16 threads/node (one float4 quad each), unroll x4.
//    out = dinv[d]*(sum h2w[s] + h2w[d]) + b2. Also resets deg/total.
__global__ void k_gather2(const float* __restrict__ b2,
                          float* __restrict__ out) {
    int gid = blockIdx.x * blockDim.x + threadIdx.x;
    int node = gid >> 4;
    int q    = gid & 15;
    if (node >= N_NODES) return;
    int row = g_rowstart[node];
    int deg = g_deg[node];
    int end = row + deg;
    if (q == 0) g_deg[node] = 0;     // reset for next call (lanes read deg above)
    if (gid == 0) g_total = 0;
    float4 acc = ((const float4*)g_h2w)[(size_t)node * 16 + q];  // self term
    int e = row;
    for (; e + 4 <= end; e += 4) {
        int s0 = g_csrc[e];
        int s1 = g_csrc[e + 1];
        int s2 = g_csrc[e + 2];
        int s3 = g_csrc[e + 3];
        float4 h0 = ((const float4*)g_h2w)[(size_t)s0 * 16 + q];
        float4 h1 = ((const float4*)g_h2w)[(size_t)s1 * 16 + q];
        float4 h2 = ((const float4*)g_h2w)[(size_t)s2 * 16 + q];
        float4 h3 = ((const float4*)g_h2w)[(size_t)s3 * 16 + q];
        acc.x += (h0.x + h1.x) + (h2.x + h3.x);
        acc.y += (h0.y + h1.y) + (h2.y + h3.y);
        acc.z += (h0.z + h1.z) + (h2.z + h3.z);
        acc.w += (h0.w + h1.w) + (h2.w + h3.w);
    }
    for (; e < end; e++) {
        float4 h = ((const float4*)g_h2w)[(size_t)g_csrc[e] * 16 + q];
        acc.x += h.x;
        acc.y += h.y;
        acc.z += h.z;
        acc.w += h.w;
    }
    float dd = g_dinv[node];
    float4 bb = __ldg(&((const float4*)b2)[q]);
    float4 o;
    o.x = fmaf(dd, acc.x, bb.x);
    o.y = fmaf(dd, acc.y, bb.y);
    o.z = fmaf(dd, acc.z, bb.z);
    o.w = fmaf(dd, acc.w, bb.w);
    ((float4*)out)[(size_t)node * 16 + q] = o;
}

extern "C" void kernel_launch(void* const* d_in, const int* in_sizes, int n_in,
                              void* d_out, int out_size) {
    const float* x  = (const float*)d_in[0];
    const int*   ei = (const int*)d_in[1];   // int64 in ref -> int32 on device (JAX x64 off)
    const float* W1 = (const float*)d_in[2];
    const float* b1 = (const float*)d_in[3];
    const float* W2 = (const float*)d_in[4];
    const float* b2 = (const float*)d_in[5];
    float* out = (float*)d_out;

    k_deg<<<(N_EDGES / 2 + 255) / 256, 256>>>(ei);
    k_assign<<<(N_NODES + 255) / 256, 256>>>(x);
    k_csr<<<(N_EDGES / 2 + 255) / 256, 256>>>(ei);
    k_h2<<<N_PAD / 128, 256>>>(W1, b1, W2);
    k_gather2<<<(N_NODES * 16 + 255) / 256, 256>>>(b2, out);
}

// round 12
// speedup vs baseline: 1.1734x; 1.1734x over previous
#include <cuda_runtime.h>
#include <stdint.h>

#define N_NODES 50000
#define N_PAD   50048   // multiple of 128 for k_h2 tiling
#define N_EDGES 800000
#define HID     128
#define OUTC    64

// ---- scratch (device globals, zero-initialized at module load; k_gather2
//      re-zeroes g_deg/g_total each call so every replay starts clean).
//      Node arrays padded to N_PAD; pad entries stay 0. ----
__device__ int   g_deg[N_PAD];
__device__ int   g_rowstart[N_PAD];
__device__ int   g_wpos[N_PAD];
__device__ int   g_csrc[N_EDGES];
__device__ int   g_total;
__device__ float g_dinv[N_PAD];
__device__ __align__(16) float    g_xw[N_PAD * 4];     // x * dinv, packed float4
__device__ __align__(16) float    g_v[N_PAD * 4];      // layer-1 result
__device__ __align__(16) uint32_t g_h2wb[N_PAD * 32];  // h2 * dinv, bf16x2 pairs

#define PACK2(d, lo, hi) asm("mov.b64 %0, {%1, %2};" : "=l"(d) : "f"(lo), "f"(hi))
#define UNPACK2(lo, hi, s) asm("mov.b64 {%0, %1}, %2;" : "=f"(lo), "=f"(hi) : "l"(s))
#define FMA2(d, a, b, c) asm("fma.rn.f32x2 %0, %1, %2, %3;" : "=l"(d) : "l"(a), "l"(b), "l"(c))
// u = {hi: bf16(hiF), lo: bf16(loF)}
#define BF16X2(u, hiF, loF) asm("cvt.rn.bf16x2.f32 %0, %1, %2;" : "=r"(u) : "f"(hiF), "f"(loF))

// 1) degree histogram on dst (REDG, no return); 2 edges/thread (best measured)
__global__ void k_deg(const int* __restrict__ ei) {
    int t = blockIdx.x * blockDim.x + threadIdx.x;
    if (t >= N_EDGES / 2) return;
    int2 d = ((const int2*)(ei + N_EDGES))[t];
    atomicAdd(&g_deg[d.x], 1);
    atomicAdd(&g_deg[d.y], 1);
}

// 2) row allocation (warp scan + 1 atomic/warp) + dinv + premultiplied xw
__global__ void k_assign(const float* __restrict__ x) {
    int i = blockIdx.x * blockDim.x + threadIdx.x;
    int lane = threadIdx.x & 31;
    int deg = (i < N_NODES) ? g_deg[i] : 0;
    int incl = deg;
    #pragma unroll
    for (int o = 1; o < 32; o <<= 1) {
        int v = __shfl_up_sync(0xffffffff, incl, o);
        if (lane >= o) incl += v;
    }
    int base = 0;
    if (lane == 31) base = atomicAdd(&g_total, incl);   // incl@31 = warp total
    base = __shfl_sync(0xffffffff, base, 31);
    if (i < N_NODES) {
        int rs = base + incl - deg;
        g_rowstart[i] = rs;
        g_wpos[i] = rs;
        float dd = rsqrtf((float)(deg + 1));
        g_dinv[i] = dd;
        float4 xw;
        xw.x = __ldg(&x[i * 3 + 0]) * dd;
        xw.y = __ldg(&x[i * 3 + 1]) * dd;
        xw.z = __ldg(&x[i * 3 + 2]) * dd;
        xw.w = 0.f;
        ((float4*)g_xw)[i] = xw;
    }
}

// 3) CSR scatter: src indices grouped by dst; 2 edges/thread (best measured)
__global__ void k_csr(const int* __restrict__ ei) {
    int t = blockIdx.x * blockDim.x + threadIdx.x;
    if (t >= N_EDGES / 2) return;
    int2 s = ((const int2*)ei)[t];
    int2 d = ((const int2*)(ei + N_EDGES))[t];
    int p0 = atomicAdd(&g_wpos[d.x], 1);
    g_csrc[p0] = s.x;
    int p1 = atomicAdd(&g_wpos[d.y], 1);
    g_csrc[p1] = s.y;
}

// 4) layer-1 gather: 8 threads/node, xw premultiplied (best measured config)
__global__ void k_gather1() {
    int gid = blockIdx.x * blockDim.x + threadIdx.x;
    int node = gid >> 3;
    int t8   = gid & 7;
    if (node >= N_NODES) return;
    int row = g_rowstart[node];
    int end = row + g_deg[node];
    float a0 = 0.f, a1 = 0.f, a2 = 0.f;
    for (int e = row + t8; e < end; e += 8) {
        float4 v = ((const float4*)g_xw)[g_csrc[e]];
        a0 += v.x;
        a1 += v.y;
        a2 += v.z;
    }
    #pragma unroll
    for (int o = 4; o > 0; o >>= 1) {   // reduce within 8-lane segment
        a0 += __shfl_down_sync(0xffffffff, a0, o, 8);
        a1 += __shfl_down_sync(0xffffffff, a1, o, 8);
        a2 += __shfl_down_sync(0xffffffff, a2, o, 8);
    }
    if (t8 == 0) {
        float4 self = ((const float4*)g_xw)[node];
        float dd = g_dinv[node];
        ((float4*)g_v)[node] = make_float4((a0 + self.x) * dd,
                                           (a1 + self.y) * dd,
                                           (a2 + self.z) * dd, 0.f);
    }
}

// 5) fused h1 (relu(v@W1+b1), smem k-major) + h2 = h1 @ W2 via fma.rn.f32x2;
//    epilogue stores h2w = h2 * dinv as bf16 pairs (cols 2j,2j+1 per word).
__global__ void __launch_bounds__(256) k_h2(const float* __restrict__ W1,
                                            const float* __restrict__ b1,
                                            const float* __restrict__ W2) {
    __shared__ float4 sW2[HID * 16];    // 32 KB
    __shared__ float  sh1T[HID * 128];  // 64 KB, [k][node]
    int tid = threadIdx.x;
    int nodeBase = blockIdx.x * 128;

    #pragma unroll 4
    for (int i = tid; i < HID * 16; i += 256) sW2[i] = ((const float4*)W2)[i];

    #pragma unroll 4
    for (int i = tid; i < 128 * 32; i += 256) {
        int node = i & 127;
        int q    = i >> 7;
        float4 v  = ((const float4*)g_v)[nodeBase + node];
        float4 w0 = __ldg(&((const float4*)W1)[0 * 32 + q]);
        float4 w1 = __ldg(&((const float4*)W1)[1 * 32 + q]);
        float4 w2 = __ldg(&((const float4*)W1)[2 * 32 + q]);
        float4 bq = __ldg(&((const float4*)b1)[q]);
        sh1T[(4 * q + 0) * 128 + node] = fmaxf(fmaf(v.x, w0.x, fmaf(v.y, w1.x, fmaf(v.z, w2.x, bq.x))), 0.f);
        sh1T[(4 * q + 1) * 128 + node] = fmaxf(fmaf(v.x, w0.y, fmaf(v.y, w1.y, fmaf(v.z, w2.y, bq.y))), 0.f);
        sh1T[(4 * q + 2) * 128 + node] = fmaxf(fmaf(v.x, w0.z, fmaf(v.y, w1.z, fmaf(v.z, w2.z, bq.z))), 0.f);
        sh1T[(4 * q + 3) * 128 + node] = fmaxf(fmaf(v.x, w0.w, fmaf(v.y, w1.w, fmaf(v.z, w2.w, bq.w))), 0.f);
    }
    __syncthreads();

    int c  = tid & 15;        // cols 4c..4c+3
    int m0 = (tid >> 4) * 8;  // nodes m0..m0+7 (4 packed pairs)

    unsigned long long acc[4][4];
    #pragma unroll
    for (int p = 0; p < 4; p++)
        #pragma unroll
        for (int cc = 0; cc < 4; cc++) acc[p][cc] = 0ull;

    #pragma unroll 2
    for (int kb = 0; kb < HID; kb += 4) {
        #pragma unroll
        for (int kk = 0; kk < 4; kk++) {
            int k = kb + kk;
            float4 w = sW2[k * 16 + c];
            unsigned long long wp[4];
            PACK2(wp[0], w.x, w.x);
            PACK2(wp[1], w.y, w.y);
            PACK2(wp[2], w.z, w.z);
            PACK2(wp[3], w.w, w.w);
            float4 ha = *(const float4*)&sh1T[k * 128 + m0];
            float4 hb = *(const float4*)&sh1T[k * 128 + m0 + 4];
            unsigned long long hp[4];
            PACK2(hp[0], ha.x, ha.y);
            PACK2(hp[1], ha.z, ha.w);
            PACK2(hp[2], hb.x, hb.y);
            PACK2(hp[3], hb.z, hb.w);
            #pragma unroll
            for (int p = 0; p < 4; p++) {
                FMA2(acc[p][0], hp[p], wp[0], acc[p][0]);
                FMA2(acc[p][1], hp[p], wp[1], acc[p][1]);
                FMA2(acc[p][2], hp[p], wp[2], acc[p][2]);
                FMA2(acc[p][3], hp[p], wp[3], acc[p][3]);
            }
        }
    }

    #pragma unroll
    for (int p = 0; p < 4; p++) {
        int n0 = nodeBase + m0 + 2 * p;
        float d0 = g_dinv[n0];
        float d1 = g_dinv[n0 + 1];
        float4 r0, r1;
        UNPACK2(r0.x, r1.x, acc[p][0]);
        UNPACK2(r0.y, r1.y, acc[p][1]);
        UNPACK2(r0.z, r1.z, acc[p][2]);
        UNPACK2(r0.w, r1.w, acc[p][3]);
        uint2 u0, u1;
        BF16X2(u0.x, r0.y * d0, r0.x * d0);   // lo=col 4c,   hi=col 4c+1
        BF16X2(u0.y, r0.w * d0, r0.z * d0);   // lo=col 4c+2, hi=col 4c+3
        BF16X2(u1.x, r1.y * d1, r1.x * d1);
        BF16X2(u1.y, r1.w * d1, r1.z * d1);
        *(uint2*)&g_h2wb[(size_t)n0 * 32 + 2 * c] = u0;
        *(uint2*)&g_h2wb[(size_t)(n0 + 1) * 32 + 2 * c] = u1;
    }
}

// 6) layer-2 gather in bf16: 8 threads/node, each owns 8 cols (uint4 = 16B).
//    out = dinv[d]*(sum h2w[s] + h2w[d]) + b2. Also resets deg/total.
__global__ void k_gather2(const float* __restrict__ b2,
                          float* __restrict__ out) {
    int gid = blockIdx.x * blockDim.x + threadIdx.x;
    int node = gid >> 3;
    int q    = gid & 7;                 // uint32 words 4q..4q+3 = cols 8q..8q+7
    if (node >= N_NODES) return;
    int row = g_rowstart[node];
    int deg = g_deg[node];
    int end = row + deg;
    if (q == 0) g_deg[node] = 0;        // reset for next call
    if (gid == 0) g_total = 0;

    float a[8];
    {   // self term
        uint4 u = *(const uint4*)&g_h2wb[(size_t)node * 32 + 4 * q];
        a[0] = __uint_as_float(u.x << 16);
        a[1] = __uint_as_float(u.x & 0xFFFF0000u);
        a[2] = __uint_as_float(u.y << 16);
        a[3] = __uint_as_float(u.y & 0xFFFF0000u);
        a[4] = __uint_as_float(u.z << 16);
        a[5] = __uint_as_float(u.z & 0xFFFF0000u);
        a[6] = __uint_as_float(u.w << 16);
        a[7] = __uint_as_float(u.w & 0xFFFF0000u);
    }
    int e = row;
    for (; e + 2 <= end; e += 2) {
        int s0 = g_csrc[e];
        int s1 = g_csrc[e + 1];
        uint4 u0 = *(const uint4*)&g_h2wb[(size_t)s0 * 32 + 4 * q];
        uint4 u1 = *(const uint4*)&g_h2wb[(size_t)s1 * 32 + 4 * q];
        a[0] += __uint_as_float(u0.x << 16)        + __uint_as_float(u1.x << 16);
        a[1] += __uint_as_float(u0.x & 0xFFFF0000u) + __uint_as_float(u1.x & 0xFFFF0000u);
        a[2] += __uint_as_float(u0.y << 16)        + __uint_as_float(u1.y << 16);
        a[3] += __uint_as_float(u0.y & 0xFFFF0000u) + __uint_as_float(u1.y & 0xFFFF0000u);
        a[4] += __uint_as_float(u0.z << 16)        + __uint_as_float(u1.z << 16);
        a[5] += __uint_as_float(u0.z & 0xFFFF0000u) + __uint_as_float(u1.z & 0xFFFF0000u);
        a[6] += __uint_as_float(u0.w << 16)        + __uint_as_float(u1.w << 16);
        a[7] += __uint_as_float(u0.w & 0xFFFF0000u) + __uint_as_float(u1.w & 0xFFFF0000u);
    }
    if (e < end) {
        uint4 u = *(const uint4*)&g_h2wb[(size_t)g_csrc[e] * 32 + 4 * q];
        a[0] += __uint_as_float(u.x << 16);
        a[1] += __uint_as_float(u.x & 0xFFFF0000u);
        a[2] += __uint_as_float(u.y << 16);
        a[3] += __uint_as_float(u.y & 0xFFFF0000u);
        a[4] += __uint_as_float(u.z << 16);
        a[5] += __uint_as_float(u.z & 0xFFFF0000u);
        a[6] += __uint_as_float(u.w << 16);
        a[7] += __uint_as_float(u.w & 0xFFFF0000u);
    }
    float dd = g_dinv[node];
    float4 bb0 = __ldg(&((const float4*)b2)[2 * q]);
    float4 bb1 = __ldg(&((const float4*)b2)[2 * q + 1]);
    float4 o0, o1;
    o0.x = fmaf(dd, a[0], bb0.x);
    o0.y = fmaf(dd, a[1], bb0.y);
    o0.z = fmaf(dd, a[2], bb0.z);
    o0.w = fmaf(dd, a[3], bb0.w);
    o1.x = fmaf(dd, a[4], bb1.x);
    o1.y = fmaf(dd, a[5], bb1.y);
    o1.z = fmaf(dd, a[6], bb1.z);
    o1.w = fmaf(dd, a[7], bb1.w);
    ((float4*)out)[(size_t)node * 16 + 2 * q] = o0;
    ((float4*)out)[(size_t)node * 16 + 2 * q + 1] = o1;
}

extern "C" void kernel_launch(void* const* d_in, const int* in_sizes, int n_in,
                              void* d_out, int out_size) {
    const float* x  = (const float*)d_in[0];
    const int*   ei = (const int*)d_in[1];   // int64 in ref -> int32 on device (JAX x64 off)
    const float* W1 = (const float*)d_in[2];
    const float* b1 = (const float*)d_in[3];
    const float* W2 = (const float*)d_in[4];
    const float* b2 = (const float*)d_in[5];
    float* out = (float*)d_out;

    k_deg<<<(N_EDGES / 2 + 255) / 256, 256>>>(ei);
    k_assign<<<(N_NODES + 255) / 256, 256>>>(x);
    k_csr<<<(N_EDGES / 2 + 255) / 256, 256>>>(ei);
    k_gather1<<<(N_NODES * 8 + 255) / 256, 256>>>();
    k_h2<<<N_PAD / 128, 256>>>(W1, b1, W2);
    k_gather2<<<(N_NODES * 8 + 255) / 256, 256>>>(b2, out);
}

// round 13
// speedup vs baseline: 1.2071x; 1.0287x over previous
#include <cuda_runtime.h>
#include <stdint.h>

#define N_NODES 50000
#define N_PAD   50048   // multiple of 128 for k_h2 tiling
#define N_EDGES 800000
#define HID     128
#define OUTC    64

// ---- scratch (device globals, zero-initialized at module load; k_gather2
//      re-zeroes g_deg/g_total/g_v each call so every replay starts clean).
//      Node arrays padded to N_PAD; pad entries stay 0. ----
__device__ int   g_deg[N_PAD];
__device__ int   g_rowstart[N_PAD];
__device__ int   g_wpos[N_PAD];
__device__ int   g_csrc[N_EDGES];
__device__ int   g_total;
__device__ float g_dinv[N_PAD];
__device__ __align__(16) float    g_xw[N_PAD * 4];     // x * dinv, packed float4
__device__ __align__(16) float    g_v[N_PAD * 4];      // layer-1 edge sums (RED target)
__device__ __align__(16) uint32_t g_h2wb[N_PAD * 32];  // h2 * dinv, bf16x2 pairs

#define PACK2(d, lo, hi) asm("mov.b64 %0, {%1, %2};" : "=l"(d) : "f"(lo), "f"(hi))
#define UNPACK2(lo, hi, s) asm("mov.b64 {%0, %1}, %2;" : "=f"(lo), "=f"(hi) : "l"(s))
#define FMA2(d, a, b, c) asm("fma.rn.f32x2 %0, %1, %2, %3;" : "=l"(d) : "l"(a), "l"(b), "l"(c))
// u = {hi: bf16(hiF), lo: bf16(loF)}
#define BF16X2(u, hiF, loF) asm("cvt.rn.bf16x2.f32 %0, %1, %2;" : "=r"(u) : "f"(hiF), "f"(loF))

// 1) degree histogram on dst (REDG, no return); 2 edges/thread (best measured)
__global__ void k_deg(const int* __restrict__ ei) {
    int t = blockIdx.x * blockDim.x + threadIdx.x;
    if (t >= N_EDGES / 2) return;
    int2 d = ((const int2*)(ei + N_EDGES))[t];
    atomicAdd(&g_deg[d.x], 1);
    atomicAdd(&g_deg[d.y], 1);
}

// 2) row allocation (warp scan + 1 atomic/warp) + dinv + premultiplied xw
__global__ void k_assign(const float* __restrict__ x) {
    int i = blockIdx.x * blockDim.x + threadIdx.x;
    int lane = threadIdx.x & 31;
    int deg = (i < N_NODES) ? g_deg[i] : 0;
    int incl = deg;
    #pragma unroll
    for (int o = 1; o < 32; o <<= 1) {
        int v = __shfl_up_sync(0xffffffff, incl, o);
        if (lane >= o) incl += v;
    }
    int base = 0;
    if (lane == 31) base = atomicAdd(&g_total, incl);   // incl@31 = warp total
    base = __shfl_sync(0xffffffff, base, 31);
    if (i < N_NODES) {
        int rs = base + incl - deg;
        g_rowstart[i] = rs;
        g_wpos[i] = rs;
        float dd = rsqrtf((float)(deg + 1));
        g_dinv[i] = dd;
        float4 xw;
        xw.x = __ldg(&x[i * 3 + 0]) * dd;
        xw.y = __ldg(&x[i * 3 + 1]) * dd;
        xw.z = __ldg(&x[i * 3 + 2]) * dd;
        xw.w = 0.f;
        ((float4*)g_xw)[i] = xw;
    }
}

// 3) FUSED CSR scatter + layer-1 scatter-aggregation.
//    Per edge: wpos fetch-add -> csrc store (CSR build for gather2), and
//    xw[s] gathered + v4-RED into g_v[d] (layer-1 aggregation, order-free).
__global__ void k_csr(const int* __restrict__ ei) {
    int t = blockIdx.x * blockDim.x + threadIdx.x;
    if (t >= N_EDGES / 2) return;
    int2 s = ((const int2*)ei)[t];
    int2 d = ((const int2*)(ei + N_EDGES))[t];
    int p0 = atomicAdd(&g_wpos[d.x], 1);
    int p1 = atomicAdd(&g_wpos[d.y], 1);
    float4 v0 = ((const float4*)g_xw)[s.x];
    float4 v1 = ((const float4*)g_xw)[s.y];
    g_csrc[p0] = s.x;
    g_csrc[p1] = s.y;
    float* q0 = g_v + (size_t)d.x * 4;
    float* q1 = g_v + (size_t)d.y * 4;
    asm volatile("red.global.add.v4.f32 [%0], {%1,%2,%3,%4};"
                 :: "l"(q0), "f"(v0.x), "f"(v0.y), "f"(v0.z), "f"(0.f) : "memory");
    asm volatile("red.global.add.v4.f32 [%0], {%1,%2,%3,%4};"
                 :: "l"(q1), "f"(v1.x), "f"(v1.y), "f"(v1.z), "f"(0.f) : "memory");
}

// 4) fused: v=(g_v+xw_self)*dinv (prologue) + h1 = relu(v@W1+b1) (smem
//    k-major) + h2 = h1 @ W2 via fma.rn.f32x2; epilogue stores h2*dinv bf16.
__global__ void __launch_bounds__(256) k_h2(const float* __restrict__ W1,
                                            const float* __restrict__ b1,
                                            const float* __restrict__ W2) {
    __shared__ float4 sW2[HID * 16];    // 32 KB
    __shared__ float  sh1T[HID * 128];  // 64 KB, [k][node]
    __shared__ float4 sv[128];          // 2 KB
    int tid = threadIdx.x;
    int nodeBase = blockIdx.x * 128;

    #pragma unroll 4
    for (int i = tid; i < HID * 16; i += 256) sW2[i] = ((const float4*)W2)[i];

    if (tid < 128) {                    // finalize layer-1 vector per node
        int gnode = nodeBase + tid;     // pad nodes: all zeros -> sv = 0
        float4 gv = ((const float4*)g_v)[gnode];
        float4 xs = ((const float4*)g_xw)[gnode];
        float dd  = g_dinv[gnode];
        sv[tid] = make_float4((gv.x + xs.x) * dd,
                              (gv.y + xs.y) * dd,
                              (gv.z + xs.z) * dd, 0.f);
    }
    __syncthreads();

    #pragma unroll 4
    for (int i = tid; i < 128 * 32; i += 256) {
        int node = i & 127;
        int q    = i >> 7;
        float4 v  = sv[node];
        float4 w0 = __ldg(&((const float4*)W1)[0 * 32 + q]);
        float4 w1 = __ldg(&((const float4*)W1)[1 * 32 + q]);
        float4 w2 = __ldg(&((const float4*)W1)[2 * 32 + q]);
        float4 bq = __ldg(&((const float4*)b1)[q]);
        sh1T[(4 * q + 0) * 128 + node] = fmaxf(fmaf(v.x, w0.x, fmaf(v.y, w1.x, fmaf(v.z, w2.x, bq.x))), 0.f);
        sh1T[(4 * q + 1) * 128 + node] = fmaxf(fmaf(v.x, w0.y, fmaf(v.y, w1.y, fmaf(v.z, w2.y, bq.y))), 0.f);
        sh1T[(4 * q + 2) * 128 + node] = fmaxf(fmaf(v.x, w0.z, fmaf(v.y, w1.z, fmaf(v.z, w2.z, bq.z))), 0.f);
        sh1T[(4 * q + 3) * 128 + node] = fmaxf(fmaf(v.x, w0.w, fmaf(v.y, w1.w, fmaf(v.z, w2.w, bq.w))), 0.f);
    }
    __syncthreads();

    int c  = tid & 15;        // cols 4c..4c+3
    int m0 = (tid >> 4) * 8;  // nodes m0..m0+7 (4 packed pairs)

    unsigned long long acc[4][4];
    #pragma unroll
    for (int p = 0; p < 4; p++)
        #pragma unroll
        for (int cc = 0; cc < 4; cc++) acc[p][cc] = 0ull;

    #pragma unroll 2
    for (int kb = 0; kb < HID; kb += 4) {
        #pragma unroll
        for (int kk = 0; kk < 4; kk++) {
            int k = kb + kk;
            float4 w = sW2[k * 16 + c];
            unsigned long long wp[4];
            PACK2(wp[0], w.x, w.x);
            PACK2(wp[1], w.y, w.y);
            PACK2(wp[2], w.z, w.z);
            PACK2(wp[3], w.w, w.w);
            float4 ha = *(const float4*)&sh1T[k * 128 + m0];
            float4 hb = *(const float4*)&sh1T[k * 128 + m0 + 4];
            unsigned long long hp[4];
            PACK2(hp[0], ha.x, ha.y);
            PACK2(hp[1], ha.z, ha.w);
            PACK2(hp[2], hb.x, hb.y);
            PACK2(hp[3], hb.z, hb.w);
            #pragma unroll
            for (int p = 0; p < 4; p++) {
                FMA2(acc[p][0], hp[p], wp[0], acc[p][0]);
                FMA2(acc[p][1], hp[p], wp[1], acc[p][1]);
                FMA2(acc[p][2], hp[p], wp[2], acc[p][2]);
                FMA2(acc[p][3], hp[p], wp[3], acc[p][3]);
            }
        }
    }

    #pragma unroll
    for (int p = 0; p < 4; p++) {
        int n0 = nodeBase + m0 + 2 * p;
        float d0 = g_dinv[n0];
        float d1 = g_dinv[n0 + 1];
        float4 r0, r1;
        UNPACK2(r0.x, r1.x, acc[p][0]);
        UNPACK2(r0.y, r1.y, acc[p][1]);
        UNPACK2(r0.z, r1.z, acc[p][2]);
        UNPACK2(r0.w, r1.w, acc[p][3]);
        uint2 u0, u1;
        BF16X2(u0.x, r0.y * d0, r0.x * d0);   // lo=col 4c,   hi=col 4c+1
        BF16X2(u0.y, r0.w * d0, r0.z * d0);   // lo=col 4c+2, hi=col 4c+3
        BF16X2(u1.x, r1.y * d1, r1.x * d1);
        BF16X2(u1.y, r1.w * d1, r1.z * d1);
        *(uint2*)&g_h2wb[(size_t)n0 * 32 + 2 * c] = u0;
        *(uint2*)&g_h2wb[(size_t)(n0 + 1) * 32 + 2 * c] = u1;
    }
}

// 5) layer-2 gather in bf16: 8 threads/node, each owns 8 cols (uint4 = 16B).
//    out = dinv[d]*(sum h2w[s] + h2w[d]) + b2. Resets deg/total/v for replay.
__global__ void k_gather2(const float* __restrict__ b2,
                          float* __restrict__ out) {
    int gid = blockIdx.x * blockDim.x + threadIdx.x;
    int node = gid >> 3;
    int q    = gid & 7;                 // uint32 words 4q..4q+3 = cols 8q..8q+7
    if (node >= N_NODES) return;
    int row = g_rowstart[node];
    int deg = g_deg[node];
    int end = row + deg;
    if (q == 0) {                       // reset for next call
        g_deg[node] = 0;
        ((float4*)g_v)[node] = make_float4(0.f, 0.f, 0.f, 0.f);
    }
    if (gid == 0) g_total = 0;

    float a[8];
    {   // self term
        uint4 u = *(const uint4*)&g_h2wb[(size_t)node * 32 + 4 * q];
        a[0] = __uint_as_float(u.x << 16);
        a[1] = __uint_as_float(u.x & 0xFFFF0000u);
        a[2] = __uint_as_float(u.y << 16);
        a[3] = __uint_as_float(u.y & 0xFFFF0000u);
        a[4] = __uint_as_float(u.z << 16);
        a[5] = __uint_as_float(u.z & 0xFFFF0000u);
        a[6] = __uint_as_float(u.w << 16);
        a[7] = __uint_as_float(u.w & 0xFFFF0000u);
    }
    int e = row;
    for (; e + 2 <= end; e += 2) {
        int s0 = g_csrc[e];
        int s1 = g_csrc[e + 1];
        uint4 u0 = *(const uint4*)&g_h2wb[(size_t)s0 * 32 + 4 * q];
        uint4 u1 = *(const uint4*)&g_h2wb[(size_t)s1 * 32 + 4 * q];
        a[0] += __uint_as_float(u0.x << 16)         + __uint_as_float(u1.x << 16);
        a[1] += __uint_as_float(u0.x & 0xFFFF0000u) + __uint_as_float(u1.x & 0xFFFF0000u);
        a[2] += __uint_as_float(u0.y << 16)         + __uint_as_float(u1.y << 16);
        a[3] += __uint_as_float(u0.y & 0xFFFF0000u) + __uint_as_float(u1.y & 0xFFFF0000u);
        a[4] += __uint_as_float(u0.z << 16)         + __uint_as_float(u1.z << 16);
        a[5] += __uint_as_float(u0.z & 0xFFFF0000u) + __uint_as_float(u1.z & 0xFFFF0000u);
        a[6] += __uint_as_float(u0.w << 16)         + __uint_as_float(u1.w << 16);
        a[7] += __uint_as_float(u0.w & 0xFFFF0000u) + __uint_as_float(u1.w & 0xFFFF0000u);
    }
    if (e < end) {
        uint4 u = *(const uint4*)&g_h2wb[(size_t)g_csrc[e] * 32 + 4 * q];
        a[0] += __uint_as_float(u.x << 16);
        a[1] += __uint_as_float(u.x & 0xFFFF0000u);
        a[2] += __uint_as_float(u.y << 16);
        a[3] += __uint_as_float(u.y & 0xFFFF0000u);
        a[4] += __uint_as_float(u.z << 16);
        a[5] += __uint_as_float(u.z & 0xFFFF0000u);
        a[6] += __uint_as_float(u.w << 16);
        a[7] += __uint_as_float(u.w & 0xFFFF0000u);
    }
    float dd = g_dinv[node];
    float4 bb0 = __ldg(&((const float4*)b2)[2 * q]);
    float4 bb1 = __ldg(&((const float4*)b2)[2 * q + 1]);
    float4 o0, o1;
    o0.x = fmaf(dd, a[0], bb0.x);
    o0.y = fmaf(dd, a[1], bb0.y);
    o0.z = fmaf(dd, a[2], bb0.z);
    o0.w = fmaf(dd, a[3], bb0.w);
    o1.x = fmaf(dd, a[4], bb1.x);
    o1.y = fmaf(dd, a[5], bb1.y);
    o1.z = fmaf(dd, a[6], bb1.z);
    o1.w = fmaf(dd, a[7], bb1.w);
    ((float4*)out)[(size_t)node * 16 + 2 * q] = o0;
    ((float4*)out)[(size_t)node * 16 + 2 * q + 1] = o1;
}

extern "C" void kernel_launch(void* const* d_in, const int* in_sizes, int n_in,
                              void* d_out, int out_size) {
    const float* x  = (const float*)d_in[0];
    const int*   ei = (const int*)d_in[1];   // int64 in ref -> int32 on device (JAX x64 off)
    const float* W1 = (const float*)d_in[2];
    const float* b1 = (const float*)d_in[3];
    const float* W2 = (const float*)d_in[4];
    const float* b2 = (const float*)d_in[5];
    float* out = (float*)d_out;

    k_deg<<<(N_EDGES / 2 + 255) / 256, 256>>>(ei);
    k_assign<<<(N_NODES + 255) / 256, 256>>>(x);
    k_csr<<<(N_EDGES / 2 + 255) / 256, 256>>>(ei);
    k_h2<<<N_PAD / 128, 256>>>(W1, b1, W2);
    k_gather2<<<(N_NODES * 8 + 255) / 256, 256>>>(b2, out);
}